// round 11
// baseline (speedup 1.0000x reference)
#include <cuda_runtime.h>
#include <cuda_bf16.h>
#include <cstdint>

#define V_DIM 128
#define N_ROWS 16384
#define N_TILES (N_ROWS / 2)                    // 8192 row-pair tiles
#define THREADS 128
#define WARPS_PER_BLOCK 4
#define GRID 592                                // 4 CTAs per SM on 148 SMs, balanced
#define STRIDE (GRID * WARPS_PER_BLOCK)         // 2368 warps
#define POS_SLOTS 132                           // 128 max positives + 4 pad

// Scratch (no device allocation allowed)
__device__ float g_partials[GRID];
__device__ int   g_ticket = 0;

struct Tile { float4 x0, t0, x1, t1; };

__device__ __forceinline__ void load_tile(const float* __restrict__ L,
                                          const float* __restrict__ T,
                                          int tile, int lane, Tile& b)
{
    size_t r0 = (size_t)tile * 2 * V_DIM;
    b.x0 = reinterpret_cast<const float4*>(L + r0)[lane];
    b.t0 = reinterpret_cast<const float4*>(T + r0)[lane];
    b.x1 = reinterpret_cast<const float4*>(L + r0 + V_DIM)[lane];
    b.t1 = reinterpret_cast<const float4*>(T + r0 + V_DIM)[lane];
}

__device__ __forceinline__ void compute_tile(const Tile& b, float* spos,
                                             int lane, unsigned lanemask_lt,
                                             float& base, float& h0, float& h1,
                                             float& prod)
{
#pragma unroll
    for (int r = 0; r < 2; r++) {
        float xs[4], ts[4];
        if (r == 0) { xs[0]=b.x0.x; xs[1]=b.x0.y; xs[2]=b.x0.z; xs[3]=b.x0.w;
                      ts[0]=b.t0.x; ts[1]=b.t0.y; ts[2]=b.t0.z; ts[3]=b.t0.w; }
        else        { xs[0]=b.x1.x; xs[1]=b.x1.y; xs[2]=b.x1.z; xs[3]=b.x1.w;
                      ts[0]=b.t1.x; ts[1]=b.t1.y; ts[2]=b.t1.z; ts[3]=b.t1.w; }

        // ---- BCE pieces ----
#pragma unroll
        for (int i = 0; i < 4; i++) {
            base += fmaxf(xs[i], 0.0f);
            base  = fmaf(-xs[i], ts[i], base);
            prod *= (1.0f + __expf(-fabsf(xs[i])));
        }

        // ---- Compact positives into smem (4 ballots + predicated STS) ----
        int cnt = 0;
#pragma unroll
        for (int i = 0; i < 4; i++) {
            bool pi = ts[i] > 0.5f;
            unsigned m = __ballot_sync(0xffffffffu, pi);
            if (pi) spos[cnt + __popc(m & lanemask_lt)] = xs[i];
            cnt += __popc(m);
        }
        if (lane < 4) spos[cnt + lane] = 1.0e30f;   // pad one group of 4
        __syncwarp();

        // ---- c[i]: arithmetic self-exclusion (positives -> -1e30) ----
        float c[4];
#pragma unroll
        for (int i = 0; i < 4; i++)
            c[i] = fmaf(ts[i], -1.0e30f, 1.0f + xs[i]);

        // ---- Hinge: warp-uniform loop, 4 positives per broadcast LDS.128 ----
        int n4 = (cnt + 3) >> 2;
        const float4* pg = reinterpret_cast<const float4*>(spos);
        for (int k4 = 0; k4 < n4; k4++) {
            float4 P = pg[k4];
            float pk[4] = {P.x, P.y, P.z, P.w};
#pragma unroll
            for (int j = 0; j < 4; j++) {
                h0 += fmaxf(c[0] - pk[j], 0.0f);
                h1 += fmaxf(c[1] - pk[j], 0.0f);
                h0 += fmaxf(c[2] - pk[j], 0.0f);
                h1 += fmaxf(c[3] - pk[j], 0.0f);
            }
        }
        __syncwarp();   // protect spos reuse by next row/tile
    }
}

__global__ __launch_bounds__(THREADS)
void fused_loss_kernel(const float* __restrict__ logits,
                       const float* __restrict__ targets,
                       float* __restrict__ out)
{
    __shared__ float s_pos[WARPS_PER_BLOCK][POS_SLOTS];
    __shared__ float s_warp[WARPS_PER_BLOCK];
    __shared__ bool  s_is_last;

    const int lane = threadIdx.x & 31;
    const int wid  = threadIdx.x >> 5;
    const unsigned lanemask_lt = (1u << lane) - 1u;
    const int warp_gid = blockIdx.x * WARPS_PER_BLOCK + wid;
    float* spos = s_pos[wid];

    float base = 0.0f, h0 = 0.0f, h1 = 0.0f;
    float prod = 1.0f;   // <= (2)^32 over at most 32 factors: fp32-safe

    // ---- Grid-stride software pipeline: double-buffered tiles ----
    Tile A, Bf;
    int t0 = warp_gid;                 // always < N_TILES (2368 < 8192)
    load_tile(logits, targets, t0, lane, A);
    int t1 = t0 + STRIDE;

    for (;;) {
        bool hasB = (t1 < N_TILES);
        if (hasB) load_tile(logits, targets, t1, lane, Bf);
        compute_tile(A, spos, lane, lanemask_lt, base, h0, h1, prod);
        if (!hasB) break;

        int t2 = t1 + STRIDE;
        bool hasA = (t2 < N_TILES);
        if (hasA) load_tile(logits, targets, t2, lane, A);
        compute_tile(Bf, spos, lane, lanemask_lt, base, h0, h1, prod);
        if (!hasA) break;

        t1 = t2 + STRIDE;
    }

    // One MUFU log per thread for the whole BCE log-sum
    float bce = base + __logf(prod);
    float v = 0.7f * bce + 0.3f * (h0 + h1);

    // ---- Warp reduce ----
#pragma unroll
    for (int o = 16; o > 0; o >>= 1)
        v += __shfl_xor_sync(0xffffffffu, v, o);
    if (lane == 0) s_warp[wid] = v;
    __syncthreads();

    // ---- Block reduce (warp 0) + publish + ticket ----
    if (wid == 0) {
        float s = (lane < WARPS_PER_BLOCK) ? s_warp[lane] : 0.0f;
#pragma unroll
        for (int o = 16; o > 0; o >>= 1)
            s += __shfl_xor_sync(0xffffffffu, s, o);
        if (lane == 0) {
            g_partials[blockIdx.x] = s;
            __threadfence();
            int t = atomicAdd(&g_ticket, 1);
            s_is_last = (t == GRID - 1);
        }
    }
    __syncthreads();

    // ---- Last block: deterministic reduction of GRID partials ----
    if (s_is_last) {
        __threadfence();
        float s = 0.0f;
        for (int i = threadIdx.x; i < GRID; i += THREADS)   // fixed order
            s += g_partials[i];
#pragma unroll
        for (int o = 16; o > 0; o >>= 1)
            s += __shfl_xor_sync(0xffffffffu, s, o);
        if (lane == 0) s_warp[wid] = s;
        __syncthreads();
        if (wid == 0) {
            float r2 = (lane < WARPS_PER_BLOCK) ? s_warp[lane] : 0.0f;
#pragma unroll
            for (int o = 16; o > 0; o >>= 1)
                r2 += __shfl_xor_sync(0xffffffffu, r2, o);
            if (lane == 0) {
                out[0] = r2 * (1.0f / ((float)V_DIM * (float)N_ROWS));
                g_ticket = 0;   // reset for graph replay
            }
        }
    }
}

extern "C" void kernel_launch(void* const* d_in, const int* in_sizes, int n_in,
                              void* d_out, int out_size)
{
    const float* logits  = (const float*)d_in[0];
    const float* targets = (const float*)d_in[1];
    float* out = (float*)d_out;

    fused_loss_kernel<<<GRID, THREADS>>>(logits, targets, out);
}

// round 12
// speedup vs baseline: 1.0488x; 1.0488x over previous
#include <cuda_runtime.h>
#include <cuda_bf16.h>
#include <cstdint>

#define V_DIM 128
#define N_ROWS 16384
#define TILE_ROWS 8
#define N_TILES (N_ROWS / TILE_ROWS)          // 2048
#define THREADS 256
#define WARPS 8
#define GRID 296                              // exactly 2 CTAs per SM (148 SMs)
#define POS_SLOTS 132                         // 128 max positives + 4 pad

// Scratch (no device allocation allowed)
__device__ float g_partials[GRID];
__device__ int   g_ticket = 0;

// ---- cp.async helpers (16B, L1-bypass) ----
__device__ __forceinline__ void cp16(uint32_t smem_addr, const void* gptr) {
    asm volatile("cp.async.cg.shared.global [%0], [%1], 16;\n"
                 :: "r"(smem_addr), "l"(gptr));
}
__device__ __forceinline__ void cp_commit() {
    asm volatile("cp.async.commit_group;\n");
}
template <int N>
__device__ __forceinline__ void cp_wait() {
    asm volatile("cp.async.wait_group %0;\n" :: "n"(N));
}

__global__ __launch_bounds__(THREADS)
void fused_loss_kernel(const float* __restrict__ logits,
                       const float* __restrict__ targets,
                       float* __restrict__ out)
{
    __shared__ float s_x[2][TILE_ROWS * V_DIM];   // 2 x 4KB
    __shared__ float s_t[2][TILE_ROWS * V_DIM];   // 2 x 4KB
    __shared__ float s_pos[WARPS][POS_SLOTS];
    __shared__ float s_warp[WARPS];
    __shared__ bool  s_is_last;

    const int tid  = threadIdx.x;
    const int lane = tid & 31;
    const int wid  = tid >> 5;
    const unsigned lanemask_lt = (1u << lane) - 1u;

    const uint32_t sx_addr[2] = { (uint32_t)__cvta_generic_to_shared(&s_x[0][tid * 4]),
                                  (uint32_t)__cvta_generic_to_shared(&s_x[1][tid * 4]) };
    const uint32_t st_addr[2] = { (uint32_t)__cvta_generic_to_shared(&s_t[0][tid * 4]),
                                  (uint32_t)__cvta_generic_to_shared(&s_t[1][tid * 4]) };

    float base = 0.0f, h0 = 0.0f, h1 = 0.0f;
    float prod = 1.0f;   // <= 2^28 over at most 28 factors: fp32-safe

    // ---- Double-buffered cp.async pipeline over grid-strided tiles ----
    int t   = blockIdx.x;        // always < N_TILES (296 < 2048)
    int nxt = t + GRID;
    int cs  = 0;

    {   // prologue: stage 0 <- tile t
        size_t off = (size_t)t * TILE_ROWS * V_DIM + tid * 4;
        cp16(sx_addr[0], logits + off);
        cp16(st_addr[0], targets + off);
        cp_commit();
    }

    while (t < N_TILES) {
        bool more = (nxt < N_TILES);
        if (more) {   // issue next tile into the other stage
            size_t off = (size_t)nxt * TILE_ROWS * V_DIM + tid * 4;
            cp16(sx_addr[cs ^ 1], logits + off);
            cp16(st_addr[cs ^ 1], targets + off);
            cp_commit();
            cp_wait<1>();        // current tile's group complete
        } else {
            cp_wait<0>();
        }
        __syncthreads();

        // ---- Compute: warp `wid` handles row `wid` of this tile ----
        const float4 xv = reinterpret_cast<const float4*>(&s_x[cs][wid * V_DIM])[lane];
        const float4 tv = reinterpret_cast<const float4*>(&s_t[cs][wid * V_DIM])[lane];
        float xs[4] = {xv.x, xv.y, xv.z, xv.w};
        float ts[4] = {tv.x, tv.y, tv.z, tv.w};

        // BCE pieces
#pragma unroll
        for (int i = 0; i < 4; i++) {
            base += fmaxf(xs[i], 0.0f);
            base  = fmaf(-xs[i], ts[i], base);
            prod *= (1.0f + __expf(-fabsf(xs[i])));
        }

        // Compact positives into s_pos[wid]
        int cnt = 0;
#pragma unroll
        for (int i = 0; i < 4; i++) {
            bool pi = ts[i] > 0.5f;
            unsigned m = __ballot_sync(0xffffffffu, pi);
            if (pi) s_pos[wid][cnt + __popc(m & lanemask_lt)] = xs[i];
            cnt += __popc(m);
        }
        if (lane < 4) s_pos[wid][cnt + lane] = 1.0e30f;   // pad one group
        __syncwarp();

        // c[i]: arithmetic self-exclusion (positives -> -1e30)
        float c[4];
#pragma unroll
        for (int i = 0; i < 4; i++)
            c[i] = fmaf(ts[i], -1.0e30f, 1.0f + xs[i]);

        // Hinge: warp-uniform loop, 4 positives per broadcast LDS.128
        int n4 = (cnt + 3) >> 2;
        const float4* pg = reinterpret_cast<const float4*>(&s_pos[wid][0]);
        for (int k4 = 0; k4 < n4; k4++) {
            float4 P = pg[k4];
            float pk[4] = {P.x, P.y, P.z, P.w};
#pragma unroll
            for (int j = 0; j < 4; j++) {
                h0 += fmaxf(c[0] - pk[j], 0.0f);
                h1 += fmaxf(c[1] - pk[j], 0.0f);
                h0 += fmaxf(c[2] - pk[j], 0.0f);
                h1 += fmaxf(c[3] - pk[j], 0.0f);
            }
        }

        __syncthreads();   // stage cs free for refill; s_pos safe for reuse
        t = nxt; nxt += GRID; cs ^= 1;
    }

    // One MUFU log per thread for the whole BCE log-sum
    float bce = base + __logf(prod);
    float v = 0.7f * bce + 0.3f * (h0 + h1);

    // ---- Warp reduce ----
#pragma unroll
    for (int o = 16; o > 0; o >>= 1)
        v += __shfl_xor_sync(0xffffffffu, v, o);
    if (lane == 0) s_warp[wid] = v;
    __syncthreads();

    // ---- Block reduce (warp 0) + publish + ticket ----
    if (wid == 0) {
        float s = (lane < WARPS) ? s_warp[lane] : 0.0f;
#pragma unroll
        for (int o = 16; o > 0; o >>= 1)
            s += __shfl_xor_sync(0xffffffffu, s, o);
        if (lane == 0) {
            g_partials[blockIdx.x] = s;
            __threadfence();
            int tk = atomicAdd(&g_ticket, 1);
            s_is_last = (tk == GRID - 1);
        }
    }
    __syncthreads();

    // ---- Last block: deterministic reduction of GRID partials ----
    if (s_is_last) {
        __threadfence();
        float s = 0.0f;
        for (int i = tid; i < GRID; i += THREADS)   // fixed order
            s += g_partials[i];
#pragma unroll
        for (int o = 16; o > 0; o >>= 1)
            s += __shfl_xor_sync(0xffffffffu, s, o);
        if (lane == 0) s_warp[wid] = s;
        __syncthreads();
        if (wid == 0) {
            float r2 = (lane < WARPS) ? s_warp[lane] : 0.0f;
#pragma unroll
            for (int o = 16; o > 0; o >>= 1)
                r2 += __shfl_xor_sync(0xffffffffu, r2, o);
            if (lane == 0) {
                out[0] = r2 * (1.0f / ((float)V_DIM * (float)N_ROWS));
                g_ticket = 0;   // reset for graph replay
            }
        }
    }
}

extern "C" void kernel_launch(void* const* d_in, const int* in_sizes, int n_in,
                              void* d_out, int out_size)
{
    const float* logits  = (const float*)d_in[0];
    const float* targets = (const float*)d_in[1];
    float* out = (float*)d_out;

    fused_loss_kernel<<<GRID, THREADS>>>(logits, targets, out);
}

// round 13
// speedup vs baseline: 1.2554x; 1.1969x over previous
#include <cuda_runtime.h>
#include <cuda_bf16.h>
#include <cstdint>

#define V_DIM 128
#define N_ROWS 16384
#define WARPS_PER_BLOCK 8
#define THREADS_PER_BLOCK (WARPS_PER_BLOCK * 32)   // 256
#define ROWS_PER_WARP 2
#define ROWS_PER_BLOCK (WARPS_PER_BLOCK * ROWS_PER_WARP)   // 16
#define N_BLOCKS (N_ROWS / ROWS_PER_BLOCK)      // 1024

// Scratch (no device allocation allowed)
__device__ unsigned long long g_sum = 0ULL;     // fixed-point (x 2^32) total
__device__ int g_ticket = 0;

__global__ __launch_bounds__(THREADS_PER_BLOCK)
void fused_loss_kernel(const float* __restrict__ logits,
                       const float* __restrict__ targets,
                       float* __restrict__ out)
{
    __shared__ float s_warp[WARPS_PER_BLOCK];

    const int lane = threadIdx.x & 31;
    const int wid  = threadIdx.x >> 5;
    // 32-bit addressing: arrays are 8MB, offsets fit easily in uint32
    const unsigned row0 = (blockIdx.x * WARPS_PER_BLOCK + wid) * ROWS_PER_WARP;
    const unsigned e0   = row0 * V_DIM + lane * 4;   // element offset of this lane

    // ---- Front-batched loads: 2 rows x (logits,targets), float4 per lane ----
    float4 xv0 = *reinterpret_cast<const float4*>(logits  + e0);
    float4 tv0 = *reinterpret_cast<const float4*>(targets + e0);
    float4 xv1 = *reinterpret_cast<const float4*>(logits  + e0 + V_DIM);
    float4 tv1 = *reinterpret_cast<const float4*>(targets + e0 + V_DIM);

    float base = 0.0f;            // sum of max(x,0) - x*t
    float h0 = 0.0f, h1 = 0.0f;   // hinge accumulators (ILP)
    float prod = 1.0f;            // product of (1 + e^-|x|): 8 factors <= 256

#pragma unroll
    for (int r = 0; r < ROWS_PER_WARP; r++) {
        float xs[4], ts[4];
        if (r == 0) { xs[0]=xv0.x; xs[1]=xv0.y; xs[2]=xv0.z; xs[3]=xv0.w;
                      ts[0]=tv0.x; ts[1]=tv0.y; ts[2]=tv0.z; ts[3]=tv0.w; }
        else        { xs[0]=xv1.x; xs[1]=xv1.y; xs[2]=xv1.z; xs[3]=xv1.w;
                      ts[0]=tv1.x; ts[1]=tv1.y; ts[2]=tv1.z; ts[3]=tv1.w; }

        // ---- BCE pieces ----
#pragma unroll
        for (int i = 0; i < 4; i++) {
            base += fmaxf(xs[i], 0.0f);
            base  = fmaf(-xs[i], ts[i], base);
            prod *= (1.0f + __expf(-fabsf(xs[i])));
        }

        // ---- c[i]: arithmetic self-exclusion (positives -> ~ -1e30) ----
        float c[4];
#pragma unroll
        for (int i = 0; i < 4; i++)
            c[i] = fmaf(ts[i], -1.0e30f, 1.0f + xs[i]);

        // ---- Hinge: shuffle-broadcast of positives (minimal instr count) ----
#pragma unroll
        for (int i = 0; i < 4; i++) {
            unsigned m = __ballot_sync(0xffffffffu, ts[i] > 0.5f);
            while (m) {                                    // warp-uniform
                int src = __ffs(m) - 1;
                m &= m - 1;
                float pv = __shfl_sync(0xffffffffu, xs[i], src);
                h0 += fmaxf(c[0] - pv, 0.0f);
                h1 += fmaxf(c[1] - pv, 0.0f);
                h0 += fmaxf(c[2] - pv, 0.0f);
                h1 += fmaxf(c[3] - pv, 0.0f);
            }
        }
    }

    // One MUFU log per thread
    float bce = base + __logf(prod);
    float v = 0.7f * bce + 0.3f * (h0 + h1);

    // ---- Warp reduce ----
#pragma unroll
    for (int o = 16; o > 0; o >>= 1)
        v += __shfl_xor_sync(0xffffffffu, v, o);
    if (lane == 0) s_warp[wid] = v;
    __syncthreads();

    // ---- Block reduce (warp 0) + exact fixed-point atomic accumulate ----
    if (wid == 0) {
        float s = (lane < WARPS_PER_BLOCK) ? s_warp[lane] : 0.0f;
#pragma unroll
        for (int o = 16; o > 0; o >>= 1)
            s += __shfl_xor_sync(0xffffffffu, s, o);
        if (lane == 0) {
            // s >= 0 (both loss terms non-negative); 2^32 scale is exact-enough
            // (quantization < 2^-32 * 1024 blocks => ~1e-7 absolute on ~3e6 sum)
            unsigned long long q = (unsigned long long)__double2ll_rn((double)s * 4294967296.0);
            atomicAdd(&g_sum, q);
            __threadfence();
            int t = atomicAdd(&g_ticket, 1);
            if (t == N_BLOCKS - 1) {
                // All block sums are in g_sum (integer adds: exact, deterministic)
                unsigned long long total = atomicAdd(&g_sum, 0ULL);
                double d = (double)(long long)total * (1.0 / 4294967296.0);
                out[0] = (float)(d / ((double)V_DIM * (double)N_ROWS));
                g_sum = 0ULL;     // reset for next graph replay
                g_ticket = 0;
            }
        }
    }
}

extern "C" void kernel_launch(void* const* d_in, const int* in_sizes, int n_in,
                              void* d_out, int out_size)
{
    const float* logits  = (const float*)d_in[0];
    const float* targets = (const float*)d_in[1];
    float* out = (float*)d_out;

    fused_loss_kernel<<<N_BLOCKS, THREADS_PER_BLOCK>>>(logits, targets, out);
}

// round 14
// speedup vs baseline: 1.4316x; 1.1404x over previous
#include <cuda_runtime.h>
#include <cuda_bf16.h>
#include <cstdint>

#define V_DIM 128
#define N_ROWS 16384
#define WARPS_PER_BLOCK 8
#define THREADS_PER_BLOCK (WARPS_PER_BLOCK * 32)   // 256
#define ROWS_PER_WARP 2
#define ROWS_PER_BLOCK (WARPS_PER_BLOCK * ROWS_PER_WARP)   // 16
#define N_BLOCKS (N_ROWS / ROWS_PER_BLOCK)      // 1024

// Scratch (no device allocation allowed)
__device__ unsigned long long g_sum = 0ULL;     // fixed-point (x 2^32) total
__device__ int g_ticket = 0;

__global__ __launch_bounds__(THREADS_PER_BLOCK)
void fused_loss_kernel(const float* __restrict__ logits,
                       const float* __restrict__ targets,
                       float* __restrict__ out)
{
    __shared__ float s_warp[WARPS_PER_BLOCK];

    const int lane = threadIdx.x & 31;
    const int wid  = threadIdx.x >> 5;
    // 32-bit addressing (arrays are 8MB)
    const unsigned row0 = (blockIdx.x * WARPS_PER_BLOCK + wid) * ROWS_PER_WARP;
    const unsigned e0   = row0 * V_DIM + lane * 4;

    // ---- Front-batched loads: 2 rows x (logits,targets), float4 per lane ----
    float4 xv0 = *reinterpret_cast<const float4*>(logits  + e0);
    float4 tv0 = *reinterpret_cast<const float4*>(targets + e0);
    float4 xv1 = *reinterpret_cast<const float4*>(logits  + e0 + V_DIM);
    float4 tv1 = *reinterpret_cast<const float4*>(targets + e0 + V_DIM);

    float xs[2][4] = {{xv0.x, xv0.y, xv0.z, xv0.w}, {xv1.x, xv1.y, xv1.z, xv1.w}};
    float ts[2][4] = {{tv0.x, tv0.y, tv0.z, tv0.w}, {tv1.x, tv1.y, tv1.z, tv1.w}};

    // ---- Hoist all 8 ballots (VOTE latency overlaps the FMA chains below) ----
    unsigned m[2][4];
#pragma unroll
    for (int r = 0; r < 2; r++)
#pragma unroll
        for (int i = 0; i < 4; i++)
            m[r][i] = __ballot_sync(0xffffffffu, ts[r][i] > 0.5f);

    // ---- BCE pieces with split accumulators (2x ILP on the serial chains) ----
    float base0 = 0.0f, base1 = 0.0f;
    float prod0 = 1.0f, prod1 = 1.0f;   // each <= 2^8 over 8 factors
#pragma unroll
    for (int i = 0; i < 4; i++) {
        base0 += fmaxf(xs[0][i], 0.0f);
        base0  = fmaf(-xs[0][i], ts[0][i], base0);
        prod0 *= (1.0f + __expf(-fabsf(xs[0][i])));
        base1 += fmaxf(xs[1][i], 0.0f);
        base1  = fmaf(-xs[1][i], ts[1][i], base1);
        prod1 *= (1.0f + __expf(-fabsf(xs[1][i])));
    }

    // ---- Hinge: shuffle-broadcast of positives; arithmetic self-exclusion ----
    float h0 = 0.0f, h1 = 0.0f;
#pragma unroll
    for (int r = 0; r < 2; r++) {
        float c[4];
#pragma unroll
        for (int i = 0; i < 4; i++)
            c[i] = fmaf(ts[r][i], -1.0e30f, 1.0f + xs[r][i]);
#pragma unroll
        for (int i = 0; i < 4; i++) {
            unsigned mm = m[r][i];
            while (mm) {                                   // warp-uniform
                int src = __ffs(mm) - 1;
                mm &= mm - 1;
                float pv = __shfl_sync(0xffffffffu, xs[r][i], src);
                h0 += fmaxf(c[0] - pv, 0.0f);
                h1 += fmaxf(c[1] - pv, 0.0f);
                h0 += fmaxf(c[2] - pv, 0.0f);
                h1 += fmaxf(c[3] - pv, 0.0f);
            }
        }
    }

    // One MUFU log per thread (prod0*prod1 <= 2^16: fp32-safe)
    float bce = (base0 + base1) + __logf(prod0 * prod1);
    float v = 0.7f * bce + 0.3f * (h0 + h1);

    // ---- Warp reduce ----
#pragma unroll
    for (int o = 16; o > 0; o >>= 1)
        v += __shfl_xor_sync(0xffffffffu, v, o);
    if (lane == 0) s_warp[wid] = v;
    __syncthreads();

    // ---- Block reduce (warp 0) + exact fixed-point atomic accumulate ----
    if (wid == 0) {
        float s = (lane < WARPS_PER_BLOCK) ? s_warp[lane] : 0.0f;
#pragma unroll
        for (int o = 16; o > 0; o >>= 1)
            s += __shfl_xor_sync(0xffffffffu, s, o);
        if (lane == 0) {
            // s >= 0; 2^32 fixed-point: exact integer accumulation => deterministic
            unsigned long long q =
                (unsigned long long)__double2ll_rn((double)s * 4294967296.0);
            atomicAdd(&g_sum, q);
            int t = atomicAdd(&g_ticket, 1);
            if (t == N_BLOCKS - 1) {
                unsigned long long total = atomicAdd(&g_sum, 0ULL);
                double d = (double)(long long)total * (1.0 / 4294967296.0);
                out[0] = (float)(d / ((double)V_DIM * (double)N_ROWS));
                g_sum = 0ULL;     // reset for next graph replay
                g_ticket = 0;
            }
        }
    }
}

extern "C" void kernel_launch(void* const* d_in, const int* in_sizes, int n_in,
                              void* d_out, int out_size)
{
    const float* logits  = (const float*)d_in[0];
    const float* targets = (const float*)d_in[1];
    float* out = (float*)d_out;

    fused_loss_kernel<<<N_BLOCKS, THREADS_PER_BLOCK>>>(logits, targets, out);
}